// round 5
// baseline (speedup 1.0000x reference)
#include <cuda_runtime.h>

// Problem constants (fixed by the reference)
#define BB 16
#define NN 1024
#define DD 1024
#define UU 512

#define NBLOCKS 1184          // 148 SMs * 8 blocks/SM, all co-resident
#define NPROD   592           // producer blocks (x-read stream)
#define NVBLK   128           // blocks computing v (16 cols each)
#define NROWS   (BB * NN)     // 16384 rows
#define NGROUPS (NROWS / 8)   // 2048 output row-groups of 8 rows

// Scratch (no cudaMalloc allowed)
__device__ float    g_v[2 * DD];        // v_h | v_m
__device__ float    g_c[2];             // c_h, c_m + b_out
__device__ float    g_s[2 * NROWS];     // sH | sM
__device__ int      g_cnt[BB];          // rows completed per batch
__device__ unsigned g_row_ticket;
__device__ unsigned g_out_ticket;
__device__ unsigned g_bar_gen = 0;      // generation barrier (launch-safe)
__device__ unsigned g_bar_cnt = 0;

__device__ __forceinline__ void grid_barrier() {
    __syncthreads();
    if (threadIdx.x == 0) {
        __threadfence();
        unsigned gen = *((volatile unsigned*)&g_bar_gen);
        if (atomicAdd(&g_bar_cnt, 1u) == NBLOCKS - 1) {
            g_bar_cnt = 0;
            __threadfence();
            atomicAdd(&g_bar_gen, 1u);          // release
        } else {
            while (*((volatile unsigned*)&g_bar_gen) == gen) __nanosleep(64);
        }
    }
    __syncthreads();
}

__global__ void __launch_bounds__(256, 8)
fused(const float* __restrict__ x,
      const float* __restrict__ W_h,
      const float* __restrict__ b_h,
      const float* __restrict__ W_m,
      const float* __restrict__ b_m,
      const float* __restrict__ w_out,
      const float* __restrict__ b_out,
      float* __restrict__ out) {
    int t    = threadIdx.x;
    int blk  = blockIdx.x;
    int lane = t & 31;

    // ---------------- Stage 0: counters reset + v + constants ----------------
    if (blk == 0 && t == 0) {
        g_row_ticket = 0;
        g_out_ticket = 0;
#pragma unroll
        for (int b = 0; b < BB; ++b) g_cnt[b] = 0;
    }

    if (blk < NVBLK) {
        // 16 full columns per block. thread: col = t&15, u-slice = t>>4 (32 u's).
        int col0 = blk * 16;                       // 0..2047 in steps of 16
        const float* __restrict__ W = (col0 < DD) ? W_h : W_m;
        int d  = (col0 & (DD - 1)) + (t & 15);
        int u0 = (t >> 4) * 32;
        float a0 = 0.f, a1 = 0.f, a2 = 0.f, a3 = 0.f;
#pragma unroll
        for (int k = 0; k < 32; k += 4) {
            a0 = fmaf(w_out[u0 + k + 0], W[(size_t)(u0 + k + 0) * DD + d], a0);
            a1 = fmaf(w_out[u0 + k + 1], W[(size_t)(u0 + k + 1) * DD + d], a1);
            a2 = fmaf(w_out[u0 + k + 2], W[(size_t)(u0 + k + 2) * DD + d], a2);
            a3 = fmaf(w_out[u0 + k + 3], W[(size_t)(u0 + k + 3) * DD + d], a3);
        }
        __shared__ float vpar[16][16];             // [uslice][col]
        vpar[t >> 4][t & 15] = (a0 + a1) + (a2 + a3);
        __syncthreads();
        if (t < 16) {
            float acc = 0.f;
#pragma unroll
            for (int k = 0; k < 16; ++k) acc += vpar[k][t];
            g_v[col0 + t] = acc;
        }
    } else if (blk == NVBLK) {
        // bias constants
        float w0 = w_out[t], w1 = w_out[t + 256];
        float h = w0 * b_h[t] + w1 * b_h[t + 256];
        float m = w0 * b_m[t] + w1 * b_m[t + 256];
#pragma unroll
        for (int o = 16; o > 0; o >>= 1) {
            h += __shfl_xor_sync(0xffffffffu, h, o);
            m += __shfl_xor_sync(0xffffffffu, m, o);
        }
        __shared__ float rh[8], rm[8];
        if (lane == 0) { rh[t >> 5] = h; rm[t >> 5] = m; }
        __syncthreads();
        if (t == 0) {
            float hh = 0.f, mm = 0.f;
#pragma unroll
            for (int k = 0; k < 8; ++k) { hh += rh[k]; mm += rm[k]; }
            g_c[0] = hh;
            g_c[1] = mm + b_out[0];
        }
    }

    grid_barrier();   // v, constants, counter resets now globally visible

    // ---------------- Stage 1: producers — warp-per-row dot products --------
    if (blk < NPROD) {
        const float4* __restrict__ vh4 = (const float4*)(g_v);
        const float4* __restrict__ vm4 = (const float4*)(g_v + DD);
        float ch = g_c[0], cm = g_c[1];
        for (;;) {
            unsigned row;
            if (lane == 0) row = atomicAdd(&g_row_ticket, 1u);
            row = __shfl_sync(0xffffffffu, row, 0);
            if (row >= NROWS) break;

            const float4* __restrict__ x4 = (const float4*)(x + (size_t)row * DD);
            float ah = 0.f, am = 0.f;
#pragma unroll
            for (int k = 0; k < 8; ++k) {
                int idx = lane + 32 * k;
                float4 xv = __ldcs(&x4[idx]);      // streaming: don't hog L2
                float4 vh = vh4[idx];
                float4 vm = vm4[idx];
                ah += xv.x * vh.x + xv.y * vh.y + xv.z * vh.z + xv.w * vh.w;
                am += xv.x * vm.x + xv.y * vm.y + xv.z * vm.z + xv.w * vm.w;
            }
#pragma unroll
            for (int o = 16; o > 0; o >>= 1) {
                ah += __shfl_xor_sync(0xffffffffu, ah, o);
                am += __shfl_xor_sync(0xffffffffu, am, o);
            }
            if (lane == 0) {
                g_s[row]         = ah + ch;
                g_s[NROWS + row] = am + cm;
                __threadfence();
                atomicAdd(&g_cnt[row >> 10], 1);
            }
        }
    }

    // ---------------- Stage 2: output writer (consumers + drained producers)-
    {
        __shared__ unsigned s_g;
        float4* __restrict__ o4 = (float4*)out;
        for (;;) {
            __syncthreads();                       // protect s_g reuse
            if (t == 0) s_g = atomicAdd(&g_out_ticket, 1u);
            __syncthreads();
            unsigned g = s_g;
            if (g >= NGROUPS) break;

            int b  = g >> 7;                       // 128 groups per batch
            int i0 = g * 8;                        // first global row (b*N+i)
            if (t == 0) {
                while (*((volatile int*)&g_cnt[b]) < NN) __nanosleep(64);
                __threadfence();                   // acquire
            }
            __syncthreads();

            float4 m = ((const float4*)(g_s + NROWS + b * NN))[t];
            float sH[8];
#pragma unroll
            for (int r = 0; r < 8; ++r) sH[r] = g_s[i0 + r];
#pragma unroll
            for (int r = 0; r < 8; ++r) {
                float4 v = make_float4(sH[r] + m.x, sH[r] + m.y,
                                       sH[r] + m.z, sH[r] + m.w);
                __stcs(&o4[(size_t)(i0 + r) * (NN / 4) + t], v);
            }
        }
    }
}

// ---------------------------------------------------------------------------
// Inputs (metadata order): x, W_h, b_h, W_m, b_m, w_out, b_out
// Output: float32 [B, N, N]
// ---------------------------------------------------------------------------
extern "C" void kernel_launch(void* const* d_in, const int* in_sizes, int n_in,
                              void* d_out, int out_size) {
    const float* x     = (const float*)d_in[0];
    const float* W_h   = (const float*)d_in[1];
    const float* b_h   = (const float*)d_in[2];
    const float* W_m   = (const float*)d_in[3];
    const float* b_m   = (const float*)d_in[4];
    const float* w_out = (const float*)d_in[5];
    const float* b_out = (const float*)d_in[6];
    float* out = (float*)d_out;

    fused<<<NBLOCKS, 256>>>(x, W_h, b_h, W_m, b_m, w_out, b_out, out);
}

// round 6
// speedup vs baseline: 1.9326x; 1.9326x over previous
#include <cuda_runtime.h>

// Problem constants (fixed by the reference)
#define BB 16
#define NN 1024
#define DD 1024
#define UU 512

#define SPLITS 64
#define UCHUNK (UU / SPLITS)   // 8
#define NROWS  (BB * NN)       // 16384

// Scratch (no cudaMalloc allowed)
__device__ float g_part[SPLITS * 2 * DD];  // partial v sums [split][2*D]
__device__ float g_v[2 * DD];              // v_h | v_m
__device__ float g_c[2];                   // c_h, c_m + b_out
__device__ float g_s[2 * NROWS];           // sH | sM

// ---------------------------------------------------------------------------
// Kernel 1: partial sums of v[col] = sum_u w_out[u]*W[u,col] over 8-u chunks.
// Blocks 0..511: 2048 cols x 64 splits, coalesced 128B warp reads, MLP=8.
// Block 512: scalar constants c_h = w.b_h, c_m = w.b_m + b_out.
// ---------------------------------------------------------------------------
__global__ void __launch_bounds__(256) vpart(const float* __restrict__ W_h,
                                             const float* __restrict__ W_m,
                                             const float* __restrict__ w_out,
                                             const float* __restrict__ b_h,
                                             const float* __restrict__ b_m,
                                             const float* __restrict__ b_out) {
    if (blockIdx.x == 512) {
        int t = threadIdx.x;
        float w0 = w_out[t], w1 = w_out[t + 256];
        float h = w0 * b_h[t] + w1 * b_h[t + 256];
        float m = w0 * b_m[t] + w1 * b_m[t + 256];
#pragma unroll
        for (int o = 16; o > 0; o >>= 1) {
            h += __shfl_xor_sync(0xffffffffu, h, o);
            m += __shfl_xor_sync(0xffffffffu, m, o);
        }
        __shared__ float rh[8], rm[8];
        if ((t & 31) == 0) { rh[t >> 5] = h; rm[t >> 5] = m; }
        __syncthreads();
        if (t == 0) {
            float hh = 0.f, mm = 0.f;
#pragma unroll
            for (int k = 0; k < 8; ++k) { hh += rh[k]; mm += rm[k]; }
            g_c[0] = hh;
            g_c[1] = mm + b_out[0];
        }
        return;
    }

    int gid = blockIdx.x * 256 + threadIdx.x;  // 0..131071
    int col = gid & (2 * DD - 1);              // 0..2047
    int s   = gid >> 11;                       // split 0..63
    const float* __restrict__ W = (col < DD) ? W_h : W_m;
    int d  = col & (DD - 1);
    int u0 = s * UCHUNK;
    float acc = 0.f;
#pragma unroll
    for (int k = 0; k < UCHUNK; ++k)
        acc = fmaf(w_out[u0 + k], W[(size_t)(u0 + k) * DD + d], acc);
    g_part[s * (2 * DD) + col] = acc;
}

// ---------------------------------------------------------------------------
// Kernel 2: reduce the 64 partials per column (fixed order -> deterministic).
// ---------------------------------------------------------------------------
__global__ void __launch_bounds__(256) vreduce() {
    int col = blockIdx.x * 256 + threadIdx.x;  // 0..2047
    float acc = 0.f;
#pragma unroll
    for (int s = 0; s < SPLITS; ++s)
        acc += g_part[s * (2 * DD) + col];
    g_v[col] = acc;
}

// ---------------------------------------------------------------------------
// Kernel 3: per row (b,n): sH = x_row.v_h + c_h ; sM = x_row.v_m + c_m.
// v_h/v_m cached in REGISTERS per warp (16 float4s), amortized over 4 rows
// per warp -> per row only the 8 x-loads hit the LSU (was 24 LDG/row).
// Block = 128 thr (4 warps), grid = 1024 (4096 warps x 4 rows = 16384).
// ---------------------------------------------------------------------------
#define RPW 4
__global__ void __launch_bounds__(128, 4) skern(const float* __restrict__ x) {
    int warp = (blockIdx.x * 128 + threadIdx.x) >> 5;  // 0..4095
    int lane = threadIdx.x & 31;

    const float4* __restrict__ vh4 = (const float4*)(g_v);
    const float4* __restrict__ vm4 = (const float4*)(g_v + DD);
    float4 vh[8], vm[8];
#pragma unroll
    for (int k = 0; k < 8; ++k) {
        vh[k] = vh4[lane + 32 * k];
        vm[k] = vm4[lane + 32 * k];
    }
    float ch = g_c[0], cm = g_c[1];

    int r0 = warp * RPW;
#pragma unroll
    for (int i = 0; i < RPW; ++i) {
        int row = r0 + i;
        const float4* __restrict__ x4 = (const float4*)(x + (size_t)row * DD);
        float ah = 0.f, am = 0.f;
#pragma unroll
        for (int k = 0; k < 8; ++k) {
            float4 xv = x4[lane + 32 * k];
            ah += xv.x * vh[k].x + xv.y * vh[k].y + xv.z * vh[k].z + xv.w * vh[k].w;
            am += xv.x * vm[k].x + xv.y * vm[k].y + xv.z * vm[k].z + xv.w * vm[k].w;
        }
#pragma unroll
        for (int o = 16; o > 0; o >>= 1) {
            ah += __shfl_xor_sync(0xffffffffu, ah, o);
            am += __shfl_xor_sync(0xffffffffu, am, o);
        }
        if (lane == 0) {
            g_s[row]         = ah + ch;
            g_s[NROWS + row] = am + cm;
        }
    }
}

// ---------------------------------------------------------------------------
// Kernel 4: scores[b,i,j] = sH[b,i] + sM[b,j]. 16 output rows per block:
// thread t loads its sM float4 once, then issues 16 INDEPENDENT float4
// stores (store MLP=16). Grid = 1024. 16 | 1024 so all rows share batch b.
// ---------------------------------------------------------------------------
__global__ void __launch_bounds__(256) outkern(float* __restrict__ out) {
    int i0 = blockIdx.x * 16;  // first (b*N + i) row of this block
    int b  = i0 >> 10;         // N = 1024
    int t  = threadIdx.x;
    float4 m = ((const float4*)(g_s + NROWS + b * NN))[t];

    float sH[16];
#pragma unroll
    for (int r = 0; r < 16; ++r) sH[r] = g_s[i0 + r];

    float4* __restrict__ o4 = (float4*)out;
#pragma unroll
    for (int r = 0; r < 16; ++r) {
        float4 v = make_float4(sH[r] + m.x, sH[r] + m.y,
                               sH[r] + m.z, sH[r] + m.w);
        o4[(size_t)(i0 + r) * (NN / 4) + t] = v;
    }
}

// ---------------------------------------------------------------------------
// Inputs (metadata order): x, W_h, b_h, W_m, b_m, w_out, b_out
// Output: float32 [B, N, N]
// ---------------------------------------------------------------------------
extern "C" void kernel_launch(void* const* d_in, const int* in_sizes, int n_in,
                              void* d_out, int out_size) {
    const float* x     = (const float*)d_in[0];
    const float* W_h   = (const float*)d_in[1];
    const float* b_h   = (const float*)d_in[2];
    const float* W_m   = (const float*)d_in[3];
    const float* b_m   = (const float*)d_in[4];
    const float* w_out = (const float*)d_in[5];
    const float* b_out = (const float*)d_in[6];
    float* out = (float*)d_out;

    vpart<<<513, 256>>>(W_h, W_m, w_out, b_h, b_m, b_out);
    vreduce<<<8, 256>>>();
    skern<<<NROWS / (RPW * 4), 128>>>(x);
    outkern<<<NROWS / 16, 256>>>(out);
}